// round 3
// baseline (speedup 1.0000x reference)
#include <cuda_runtime.h>

#define BETA 0.95f
#define NSTEPS 25

__global__ __launch_bounds__(64)
void Net_91164975824989_kernel(
    const float* __restrict__ x,
    const float* __restrict__ W1, const float* __restrict__ b1,
    const float* __restrict__ W2, const float* __restrict__ b2,
    const float* __restrict__ W3, const float* __restrict__ b3,
    const float* __restrict__ W4, const float* __restrict__ b4,
    float* __restrict__ out, int B)
{
    __shared__ float h1s[8][30];
    __shared__ float h2s[8][30];
    __shared__ float Tx[8];
    __shared__ float cf[8];

    const int tid = threadIdx.x;
    const int b   = blockIdx.x * blockDim.x + tid;
    const bool active = (b < B);

    // ---- issue input loads early (overlap DRAM latency with preamble) ----
    float v[9];
    #pragma unroll
    for (int j = 0; j < 9; j++)
        v[j] = active ? __ldg(&x[b * 9 + j]) : 0.0f;

    // ================= preamble: 8-entry table -> multilinear coeffs ======
    const int pp = tid >> 3;   // pattern 0..7
    const int ln = tid & 7;    // covers neurons ln, ln+8, ln+16, ln+24

    {   // Layer 1
        float s0 = (float)( pp       & 1);
        float s1 = (float)((pp >> 1) & 1);
        float s2 = (float)((pp >> 2) & 1);
        #pragma unroll
        for (int k = 0; k < 32; k += 8) {
            int n = ln + k;
            if (n < 30) {
                float a = b1[n] + W1[n*3+0]*s0 + W1[n*3+1]*s1 + W1[n*3+2]*s2;
                h1s[pp][n] = fmaxf(a, 0.0f);
            }
        }
    }
    __syncthreads();

    {   // Layer 2: 30x30
        #pragma unroll
        for (int k = 0; k < 32; k += 8) {
            int n = ln + k;
            if (n < 30) {
                float a = b2[n];
                #pragma unroll
                for (int g = 0; g < 30; g++) a += W2[n*30+g] * h1s[pp][g];
                h2s[pp][n] = fmaxf(a, 0.0f);
            }
        }
    }
    __syncthreads();

    if (tid < 8) {   // Layers 3,4 + softmax
        int p = tid;
        float h3[3];
        #pragma unroll
        for (int o = 0; o < 3; o++) {
            float a = b3[o];
            #pragma unroll
            for (int g = 0; g < 30; g++) a += W3[o*30+g] * h2s[p][g];
            h3[o] = fmaxf(a, 0.0f);
        }
        float o0 = fmaxf(b4[0] + W4[0]*h3[0] + W4[1]*h3[1] + W4[2]*h3[2], 0.0f);
        float o1 = fmaxf(b4[1] + W4[3]*h3[0] + W4[4]*h3[1] + W4[5]*h3[2], 0.0f);
        float m  = fmaxf(o0, o1);
        float e0 = expf(o0 - m);
        float e1 = expf(o1 - m);
        Tx[p] = e0 / (e0 + e1);
    }
    __syncthreads();

    if (tid == 0) {  // multilinear coefficients; pattern index = b0 | b1<<1 | b2<<2
        float t0=Tx[0], t1=Tx[1], t2=Tx[2], t3=Tx[3];
        float t4=Tx[4], t5=Tx[5], t6=Tx[6], t7=Tx[7];
        cf[0] = t0;
        cf[1] = t1 - t0;
        cf[2] = t2 - t0;
        cf[3] = t4 - t0;
        cf[4] = t3 - t1 - t2 + t0;
        cf[5] = t5 - t1 - t4 + t0;
        cf[6] = t6 - t2 - t4 + t0;
        cf[7] = t7 - t3 - t5 - t6 + t1 + t2 + t4 - t0;
    }
    __syncthreads();

    const float c0 = cf[0], cA = cf[1], cB = cf[2], cC = cf[3];
    const float cAB = cf[4], cAC = cf[5], cBC = cf[6], cABC = cf[7];

    // ================= LIF dynamics: 25-bit spike trains ==================
    // Critical path per step: FFMA(4) -> FADD(4) -> FSEL(4) = 12 cycles.
    // FSETP + predicated OR are off the mem chain (9-way neuron ILP hides them).
    float mem[9];
    unsigned st[9];
    bool sp[9];
    #pragma unroll
    for (int j = 0; j < 9; j++) { mem[j] = 0.0f; st[j] = 0u; sp[j] = false; }

    #pragma unroll
    for (int t = 0; t < NSTEPS; t++) {
        #pragma unroll
        for (int j = 0; j < 9; j++) {
            float m0 = fmaf(BETA, mem[j], v[j]);
            float m1 = m0 - 1.0f;                 // value identical to R2's predicated path
            float m  = sp[j] ? m1 : m0;           // FSEL: pred-as-data, lat 4
            mem[j] = m;
            bool q = m > 1.0f;
            if (q) st[j] |= (1u << t);
            sp[j] = q;
        }
    }

    // ================= grouped popcount epilogue ==========================
    int pc[9];
    #pragma unroll
    for (int j = 0; j < 9; j++) pc[j] = __popc(st[j]);

    // singles grouped by coefficient (weight_j = s1[j%3] + s1[j/3])
    int sA = 2*pc[0] + pc[1] + pc[2] + pc[3] + pc[6];
    int sB = 2*pc[4] + pc[1] + pc[3] + pc[5] + pc[7];
    int sC = 2*pc[8] + pc[2] + pc[6] + pc[5] + pc[7];

    int nAB = 0, nAC = 0, nBC = 0, nABC = 0;
    #pragma unroll
    for (int r = 0; r < 3; r++) {        // rows
        unsigned a = st[3*r], bb = st[3*r+1], c = st[3*r+2];
        unsigned ab = a & bb;
        nAB  += __popc(ab);
        nAC  += __popc(a & c);
        nBC  += __popc(bb & c);
        nABC += __popc(ab & c);
    }
    #pragma unroll
    for (int q = 0; q < 3; q++) {        // cols
        unsigned a = st[q], bb = st[q+3], c = st[q+6];
        unsigned ab = a & bb;
        nAB  += __popc(ab);
        nAC  += __popc(a & c);
        nBC  += __popc(bb & c);
        nABC += __popc(ab & c);
    }

    float accx = 150.0f * c0;
    accx = fmaf(cA,   (float)sA,   accx);
    accx = fmaf(cB,   (float)sB,   accx);
    accx = fmaf(cC,   (float)sC,   accx);
    accx = fmaf(cAB,  (float)nAB,  accx);
    accx = fmaf(cAC,  (float)nAC,  accx);
    accx = fmaf(cBC,  (float)nBC,  accx);
    accx = fmaf(cABC, (float)nABC, accx);

    if (active) {
        reinterpret_cast<float2*>(out)[b] = make_float2(accx, 150.0f - accx);
    }
}

extern "C" void kernel_launch(void* const* d_in, const int* in_sizes, int n_in,
                              void* d_out, int out_size) {
    const float* x  = (const float*)d_in[0];
    const float* W1 = (const float*)d_in[1];
    const float* b1 = (const float*)d_in[2];
    const float* W2 = (const float*)d_in[3];
    const float* b2 = (const float*)d_in[4];
    const float* W3 = (const float*)d_in[5];
    const float* b3 = (const float*)d_in[6];
    const float* W4 = (const float*)d_in[7];
    const float* b4 = (const float*)d_in[8];
    float* out = (float*)d_out;

    int B = in_sizes[0] / 9;
    int threads = 64;
    int blocks = (B + threads - 1) / threads;

    Net_91164975824989_kernel<<<blocks, threads>>>(
        x, W1, b1, W2, b2, W3, b3, W4, b4, out, B);
}